// round 16
// baseline (speedup 1.0000x reference)
#include <cuda_runtime.h>
#include <cuda_fp16.h>
#include <cstdint>

#define N_NODES 50000
#define D 128
#define N_EDGES 500000
#define TILE_M 128
#define NTILES ((N_NODES + TILE_M - 1) / TILE_M)   // 391
#define GRID   148
#define NTHREADS 512

#define BSHIFT 6
#define NBUCK  ((N_NODES + 63) >> BSHIFT)          // 782

// Scratch (no cudaMalloc).
__device__ __half g_bufH2[N_NODES * D];
__device__ __half g_bufG1[N_NODES * D];
__device__ int    g_cnt[NBUCK];
__device__ int    g_off[NBUCK + 1];
__device__ int    g_cur[NBUCK];
__device__ int2   g_sa[N_EDGES];
__device__ int    g_eid[N_EDGES];

// ---- smem (bytes). fp16 tiles, 136 halves/row ----
#define HS     136
#define SM_ZN  0
#define SM_H1  34816
#define SM_W1  69632
#define SM_W2  104448
#define SM_BW  139264
#define SM_PAR 174080                // 512 floats
#define SM_RED 176128                // 512 floats (sum 256 + sq 256)
#define SM_TOT 178176                // 1 CTA/SM

__device__ __forceinline__ void mma_f16(float& d0, float& d1, float& d2, float& d3,
                                        uint32_t a0, uint32_t a1, uint32_t a2,
                                        uint32_t a3, uint32_t b0, uint32_t b1) {
    asm volatile(
        "mma.sync.aligned.m16n8k16.row.col.f32.f16.f16.f32 "
        "{%0,%1,%2,%3}, {%4,%5,%6,%7}, {%8,%9}, {%0,%1,%2,%3};"
        : "+f"(d0), "+f"(d1), "+f"(d2), "+f"(d3)
        : "r"(a0), "r"(a1), "r"(a2), "r"(a3), "r"(b0), "r"(b1));
}

#define LDMATRIX_X4(r0, r1, r2, r3, addr)                                   \
    asm volatile(                                                           \
        "ldmatrix.sync.aligned.m8n8.x4.shared.b16 {%0,%1,%2,%3}, [%4];"     \
        : "=r"(r0), "=r"(r1), "=r"(r2), "=r"(r3) : "r"(addr))

__device__ __forceinline__ uint32_t smem_u32(const void* p) {
    return (uint32_t)__cvta_generic_to_shared(p);
}

__device__ __forceinline__ float warp_sum(float v) {
#pragma unroll
    for (int o = 16; o > 0; o >>= 1) v += __shfl_xor_sync(0xffffffffu, v, o);
    return v;
}

// Single-B mainloop (pass 3): warp tile 16 rows x 64 cols.
__device__ __forceinline__ void mma_pass(const __half* __restrict__ A,
                                         const __half* __restrict__ B,
                                         float acc[8][4],
                                         int wr, int wc, int lane) {
#pragma unroll
    for (int nt = 0; nt < 8; nt++)
#pragma unroll
        for (int j = 0; j < 4; j++) acc[nt][j] = 0.f;

    const int a_row_off = lane & 15;
    const int a_col     = (lane >> 4) * 8;
    const int b_row_off = (lane & 7) + ((lane >= 16) ? 8 : 0);
    const int b_col     = (lane & 8) ? 8 : 0;

    uint32_t aAddr = smem_u32(&A[(wr * 16 + a_row_off) * HS + a_col]);
    uint32_t bAddr[4];
#pragma unroll
    for (int p = 0; p < 4; p++)
        bAddr[p] = smem_u32(&B[(wc * 64 + p * 16 + b_row_off) * HS + b_col]);

#pragma unroll
    for (int kk = 0; kk < 8; kk++) {
        const uint32_t koff = kk * 32;
        uint32_t a0, a1, a2, a3;
        LDMATRIX_X4(a0, a1, a2, a3, aAddr + koff);
        uint32_t b[4][4];
#pragma unroll
        for (int p = 0; p < 4; p++)
            LDMATRIX_X4(b[p][0], b[p][1], b[p][2], b[p][3], bAddr[p] + koff);
#pragma unroll
        for (int p = 0; p < 4; p++)
#pragma unroll
            for (int sub = 0; sub < 2; sub++) {
                int nt = 2 * p + sub;
                mma_f16(acc[nt][0], acc[nt][1], acc[nt][2], acc[nt][3],
                        a0, a1, a2, a3, b[p][2 * sub], b[p][2 * sub + 1]);
            }
    }
}

// Dual-B mainloop (passes 1+2 fused): A fragments loaded ONCE, two acc sets.
__device__ __forceinline__ void mma_pass_dual(const __half* __restrict__ A,
                                              const __half* __restrict__ B1,
                                              const __half* __restrict__ B2,
                                              float acc1[8][4], float acc2[8][4],
                                              int wr, int wc, int lane) {
#pragma unroll
    for (int nt = 0; nt < 8; nt++)
#pragma unroll
        for (int j = 0; j < 4; j++) { acc1[nt][j] = 0.f; acc2[nt][j] = 0.f; }

    const int a_row_off = lane & 15;
    const int a_col     = (lane >> 4) * 8;
    const int b_row_off = (lane & 7) + ((lane >= 16) ? 8 : 0);
    const int b_col     = (lane & 8) ? 8 : 0;

    uint32_t aAddr = smem_u32(&A[(wr * 16 + a_row_off) * HS + a_col]);
    uint32_t b1Addr[4], b2Addr[4];
#pragma unroll
    for (int p = 0; p < 4; p++) {
        int roff = (wc * 64 + p * 16 + b_row_off) * HS + b_col;
        b1Addr[p] = smem_u32(&B1[roff]);
        b2Addr[p] = smem_u32(&B2[roff]);
    }

#pragma unroll
    for (int kk = 0; kk < 8; kk++) {
        const uint32_t koff = kk * 32;
        uint32_t a0, a1, a2, a3;
        LDMATRIX_X4(a0, a1, a2, a3, aAddr + koff);
#pragma unroll
        for (int p = 0; p < 4; p++) {
            uint32_t b0r, b1r, b2r, b3r;
            LDMATRIX_X4(b0r, b1r, b2r, b3r, b1Addr[p] + koff);
            mma_f16(acc1[2*p][0], acc1[2*p][1], acc1[2*p][2], acc1[2*p][3],
                    a0, a1, a2, a3, b0r, b1r);
            mma_f16(acc1[2*p+1][0], acc1[2*p+1][1], acc1[2*p+1][2], acc1[2*p+1][3],
                    a0, a1, a2, a3, b2r, b3r);
        }
#pragma unroll
        for (int p = 0; p < 4; p++) {
            uint32_t b0r, b1r, b2r, b3r;
            LDMATRIX_X4(b0r, b1r, b2r, b3r, b2Addr[p] + koff);
            mma_f16(acc2[2*p][0], acc2[2*p][1], acc2[2*p][2], acc2[2*p][3],
                    a0, a1, a2, a3, b0r, b1r);
            mma_f16(acc2[2*p+1][0], acc2[2*p+1][1], acc2[2*p+1][2], acc2[2*p+1][3],
                    a0, a1, a2, a3, b2r, b3r);
        }
    }
}

// relu+bias+LN epilogue (16-row warp tile). TO_SMEM: fp16 -> H1; else gmem.
template <bool TO_SMEM>
__device__ __forceinline__ void epilogue_ln(
    float acc[8][4], const float* __restrict__ s_bias,
    const float* __restrict__ s_nw, const float* __restrict__ s_nb,
    float* __restrict__ red_sum, float* __restrict__ red_sq,
    __half* __restrict__ H1, __half* __restrict__ gout,
    int row0, int nrows, int wr, int wc, int q, int tig) {
    float sums[2] = {0.f, 0.f}, sqs[2] = {0.f, 0.f};
#pragma unroll
    for (int nt = 0; nt < 8; nt++) {
        int c = wc * 64 + nt * 8 + 2 * tig;
        float x0 = fmaxf(acc[nt][0] + s_bias[c], 0.f);
        float x1 = fmaxf(acc[nt][1] + s_bias[c + 1], 0.f);
        float y0 = fmaxf(acc[nt][2] + s_bias[c], 0.f);
        float y1 = fmaxf(acc[nt][3] + s_bias[c + 1], 0.f);
        acc[nt][0] = x0; acc[nt][1] = x1; acc[nt][2] = y0; acc[nt][3] = y1;
        sums[0] += x0 + x1; sqs[0] += x0 * x0 + x1 * x1;
        sums[1] += y0 + y1; sqs[1] += y0 * y0 + y1 * y1;
    }
#pragma unroll
    for (int o = 1; o <= 2; o <<= 1)
#pragma unroll
        for (int h = 0; h < 2; h++) {
            sums[h] += __shfl_xor_sync(0xffffffffu, sums[h], o);
            sqs[h]  += __shfl_xor_sync(0xffffffffu, sqs[h], o);
        }
    if (tig == 0) {
#pragma unroll
        for (int h = 0; h < 2; h++) {
            int r = wr * 16 + q + h * 8;
            red_sum[wc * 128 + r] = sums[h];
            red_sq[wc * 128 + r]  = sqs[h];
        }
    }
    __syncthreads();
    float mu[2], rs[2];
#pragma unroll
    for (int h = 0; h < 2; h++) {
        int r = wr * 16 + q + h * 8;
        float ts = red_sum[r] + red_sum[128 + r];
        float tq = red_sq[r] + red_sq[128 + r];
        float m = ts * (1.0f / 128.0f);
        mu[h] = m;
        rs[h] = rsqrtf(tq * (1.0f / 128.0f) - m * m + 1e-5f);
    }
#pragma unroll
    for (int nt = 0; nt < 8; nt++) {
        int c = wc * 64 + nt * 8 + 2 * tig;
        float nw0 = s_nw[c], nw1 = s_nw[c + 1];
        float nb0 = s_nb[c], nb1 = s_nb[c + 1];
#pragma unroll
        for (int h = 0; h < 2; h++) {
            int r = wr * 16 + q + h * 8;
            float v0 = (acc[nt][2 * h]     - mu[h]) * rs[h] * nw0 + nb0;
            float v1 = (acc[nt][2 * h + 1] - mu[h]) * rs[h] * nw1 + nb1;
            if (TO_SMEM) {
                *reinterpret_cast<__half2*>(&H1[r * HS + c]) =
                    __floats2half2_rn(v0, v1);
            } else {
                int gr = row0 + r;
                if (gr < nrows)
                    *reinterpret_cast<__half2*>(gout + (size_t)gr * D + c) =
                        __floats2half2_rn(v0, v1);
            }
        }
    }
}

// Persistent fused kernel: 148 CTAs x 512 threads, all weights resident.
__global__ void __launch_bounds__(NTHREADS, 1) fused_kernel(
    const float* __restrict__ z,
    const float* __restrict__ w1, const float* __restrict__ b1,
    const float* __restrict__ w2, const float* __restrict__ b2,
    const float* __restrict__ bw,
    const float* __restrict__ nw, const float* __restrict__ nb,
    __half* __restrict__ h2_out, __half* __restrict__ g1_out, int nrows) {
    extern __shared__ char smem[];
    __half* ZNh = reinterpret_cast<__half*>(smem + SM_ZN);
    __half* H1h = reinterpret_cast<__half*>(smem + SM_H1);
    __half* W1h = reinterpret_cast<__half*>(smem + SM_W1);
    __half* W2h = reinterpret_cast<__half*>(smem + SM_W2);
    __half* BWh = reinterpret_cast<__half*>(smem + SM_BW);
    float*  par = reinterpret_cast<float*>(smem + SM_PAR);
    float*  red_sum = reinterpret_cast<float*>(smem + SM_RED);
    float*  red_sq  = red_sum + 256;

    const int tid  = threadIdx.x;
    const int lane = tid & 31;
    const int w    = tid >> 5;
    const int q    = lane >> 2;
    const int tig  = lane & 3;
    const int wr   = w & 7;
    const int wc   = w >> 3;

    if (tid < 512)
        par[tid] = (tid < 128)   ? b1[tid]
                 : (tid < 256)   ? b2[tid - 128]
                 : (tid < 384)   ? nw[tid - 256]
                                 : nb[tid - 384];
#pragma unroll
    for (int i = 0; i < 8; i++) {
        int idx = tid + i * NTHREADS;
        int r = idx >> 5, c4 = idx & 31;
        float4 v1 = reinterpret_cast<const float4*>(w1)[idx];
        float4 v2 = reinterpret_cast<const float4*>(w2)[idx];
        int off = r * HS + c4 * 4;
        *reinterpret_cast<__half2*>(&W1h[off])     = __floats2half2_rn(v1.x, v1.y);
        *reinterpret_cast<__half2*>(&W1h[off + 2]) = __floats2half2_rn(v1.z, v1.w);
        *reinterpret_cast<__half2*>(&W2h[off])     = __floats2half2_rn(v2.x, v2.y);
        *reinterpret_cast<__half2*>(&W2h[off + 2]) = __floats2half2_rn(v2.z, v2.w);
    }
#pragma unroll
    for (int i = 0; i < 32; i++) {
        int idx = tid + i * NTHREADS;
        int d = idx >> 7, f = idx & 127;
        BWh[f * HS + d] = __float2half_rn(bw[idx]);
    }
    __syncthreads();

    const float* s_b1 = par;
    const float* s_b2 = par + 128;
    const float* s_nw = par + 256;
    const float* s_nb = par + 384;

    float4 lnw4 = reinterpret_cast<const float4*>(s_nw)[lane];
    float4 lnb4 = reinterpret_cast<const float4*>(s_nb)[lane];

    for (int t = blockIdx.x; t < NTILES; t += GRID) {
        const int row0 = t * TILE_M;
#pragma unroll
        for (int bb2 = 0; bb2 < 2; bb2++) {
            float4 v[4];
#pragma unroll
            for (int i = 0; i < 4; i++) {
                int gr = row0 + w * 8 + bb2 * 4 + i;
                v[i] = (gr < nrows)
                         ? reinterpret_cast<const float4*>(z)[(size_t)gr * 32 + lane]
                         : make_float4(0.f, 0.f, 0.f, 0.f);
            }
#pragma unroll
            for (int i = 0; i < 4; i++) {
                int r = w * 8 + bb2 * 4 + i;
                float s  = warp_sum(v[i].x + v[i].y + v[i].z + v[i].w);
                float sq = warp_sum(v[i].x * v[i].x + v[i].y * v[i].y +
                                    v[i].z * v[i].z + v[i].w * v[i].w);
                float mu = s * (1.0f / 128.0f);
                float rs = rsqrtf(sq * (1.0f / 128.0f) - mu * mu + 1e-5f);
                float o0 = (v[i].x - mu) * rs * lnw4.x + lnb4.x;
                float o1 = (v[i].y - mu) * rs * lnw4.y + lnb4.y;
                float o2 = (v[i].z - mu) * rs * lnw4.z + lnb4.z;
                float o3 = (v[i].w - mu) * rs * lnw4.w + lnb4.w;
                int off = r * HS + lane * 4;
                *reinterpret_cast<__half2*>(&ZNh[off])     = __floats2half2_rn(o0, o1);
                *reinterpret_cast<__half2*>(&ZNh[off + 2]) = __floats2half2_rn(o2, o3);
            }
        }
        __syncthreads();

        float acc1[8][4], acc2[8][4];
        mma_pass_dual(ZNh, W1h, W2h, acc1, acc2, wr, wc, lane);
        epilogue_ln<true>(acc1, s_b1, s_nw, s_nb, red_sum, red_sq, H1h, nullptr,
                          row0, nrows, wr, wc, q, tig);
        __syncthreads();
        epilogue_ln<false>(acc2, s_b2, s_nw, s_nb, red_sum, red_sq, nullptr,
                           h2_out, row0, nrows, wr, wc, q, tig);

        mma_pass(H1h, BWh, acc1, wr, wc, lane);
#pragma unroll
        for (int nt = 0; nt < 8; nt++) {
            int c = wc * 64 + nt * 8 + 2 * tig;
#pragma unroll
            for (int h = 0; h < 2; h++) {
                int gr = row0 + wr * 16 + q + h * 8;
                if (gr < nrows)
                    *reinterpret_cast<__half2*>(g1_out + (size_t)gr * D + c) =
                        __floats2half2_rn(acc1[nt][2 * h], acc1[nt][2 * h + 1]);
            }
        }
    }
}

// ---------------- bucket sort of edges by a0>>6 ----------------
__global__ void zero_kernel() {
    int i = threadIdx.x;
    for (; i < NBUCK; i += 1024) g_cnt[i] = 0;
}

#define HIST_EPB 4096
__global__ void __launch_bounds__(256) hist_kernel(const int* __restrict__ arcs) {
    __shared__ int sh[NBUCK];
    int tid = threadIdx.x;
    for (int i = tid; i < NBUCK; i += 256) sh[i] = 0;
    __syncthreads();
    int e0 = blockIdx.x * HIST_EPB;
    int e1 = min(e0 + HIST_EPB, N_EDGES);
    for (int e = e0 + tid; e < e1; e += 256)
        atomicAdd(&sh[arcs[2 * e] >> BSHIFT], 1);
    __syncthreads();
    for (int i = tid; i < NBUCK; i += 256)
        if (sh[i]) atomicAdd(&g_cnt[i], sh[i]);
}

__global__ void __launch_bounds__(1024) scan_kernel() {
    __shared__ int buf[2][1024];
    int i = threadIdx.x;
    int v = (i < NBUCK) ? g_cnt[i] : 0;
    buf[0][i] = v;
    __syncthreads();
    int cur = 0;
#pragma unroll
    for (int off = 1; off < 1024; off <<= 1) {
        int x = buf[cur][i];
        if (i >= off) x += buf[cur][i - off];
        buf[cur ^ 1][i] = x;
        cur ^= 1;
        __syncthreads();
    }
    if (i < NBUCK) {
        int excl = buf[cur][i] - v;
        g_off[i] = excl;
        g_cur[i] = excl;
        if (i == NBUCK - 1) g_off[NBUCK] = buf[cur][i];
    }
}

__global__ void __launch_bounds__(256) scatter_kernel(const int* __restrict__ arcs) {
    int e = blockIdx.x * 256 + threadIdx.x;
    if (e >= N_EDGES) return;
    int a0 = arcs[2 * e];
    int a1 = arcs[2 * e + 1];
    int pos = atomicAdd(&g_cur[a0 >> BSHIFT], 1);
    g_sa[pos] = make_int2(a0, a1);
    g_eid[pos] = e;
}

// ---------------------------------------------------------------------------
// Edge kernel v6: one CTA per bucket of 64 source nodes; G1 rows staged in
// smem (read once from L2), H2 gathered from L2. 16 edges/warp-iteration.
// ---------------------------------------------------------------------------
__global__ void __launch_bounds__(256) edge2_kernel(
    const __half* __restrict__ G1,
    const __half* __restrict__ H2,
    const float* __restrict__ bilb,
    float* __restrict__ out) {
    __shared__ float4 Gs[64 * 16];   // 16KB
    const int b     = blockIdx.x;
    const int node0 = b << BSHIFT;
    const int tid   = threadIdx.x;
    const int lane  = tid & 31;
    const int w     = tid >> 5;
    const int j     = lane >> 3;   // edge-in-batch (0..3)
    const int s     = lane & 7;    // sub-lane within edge

    // stage G1 rows of this bucket (row = 256B = 16 float4)
    int nloc = min(64, N_NODES - node0);
    for (int idx = tid; idx < nloc * 16; idx += 256) {
        int r = idx >> 4, c = idx & 15;
        Gs[r * 16 + c] =
            __ldcg(reinterpret_cast<const float4*>(G1 + (size_t)(node0 + r) * D) + c);
    }
    int start = g_off[b];
    int end   = g_off[b + 1];
    __syncthreads();

    float bbv = bilb[0];
    for (int base = start + w * 16; base < end; base += 8 * 16) {
        int2 A[4];
        int  EID[4];
        bool val[4];
#pragma unroll
        for (int k = 0; k < 4; k++) {
            int e  = base + k * 4 + j;
            val[k] = (e < end);
            int ei = val[k] ? e : start;
            A[k]   = g_sa[ei];
            EID[k] = g_eid[ei];
        }
        float4 gv[4][2], hv[4][2];
#pragma unroll
        for (int k = 0; k < 4; k++) {
            const float4* h4 =
                reinterpret_cast<const float4*>(H2 + (size_t)A[k].y * D);
            hv[k][0] = __ldcg(h4 + s);
            hv[k][1] = __ldcg(h4 + s + 8);
            int lr = A[k].x - node0;
            gv[k][0] = Gs[lr * 16 + s];
            gv[k][1] = Gs[lr * 16 + s + 8];
        }
#pragma unroll
        for (int k = 0; k < 4; k++) {
            float v = 0.f;
#pragma unroll
            for (int p = 0; p < 2; p++) {
                const __half2* gh = reinterpret_cast<const __half2*>(&gv[k][p]);
                const __half2* hh = reinterpret_cast<const __half2*>(&hv[k][p]);
#pragma unroll
                for (int kk = 0; kk < 4; kk++) {
                    float2 gf = __half22float2(gh[kk]);
                    float2 hf = __half22float2(hh[kk]);
                    v += gf.x * hf.x + gf.y * hf.y;
                }
            }
            v += __shfl_xor_sync(0xffffffffu, v, 1);
            v += __shfl_xor_sync(0xffffffffu, v, 2);
            v += __shfl_xor_sync(0xffffffffu, v, 4);
            if (s == 0 && val[k]) out[EID[k]] = v + bbv;
        }
    }
}

// ---------------------------------------------------------------------------
extern "C" void kernel_launch(void* const* d_in, const int* in_sizes, int n_in,
                              void* d_out, int out_size) {
    const float* z    = (const float*)d_in[0];
    const int*   arcs = (const int*)d_in[1];
    const float* w1   = (const float*)d_in[2];
    const float* b1   = (const float*)d_in[3];
    const float* w2   = (const float*)d_in[4];
    const float* b2   = (const float*)d_in[5];
    const float* bw   = (const float*)d_in[6];
    const float* bb   = (const float*)d_in[7];
    const float* nw   = (const float*)d_in[8];
    const float* nb   = (const float*)d_in[9];
    float*       out  = (float*)d_out;

    __half *h2buf, *g1buf;
    cudaGetSymbolAddress((void**)&h2buf, g_bufH2);
    cudaGetSymbolAddress((void**)&g1buf, g_bufG1);

    cudaFuncSetAttribute(fused_kernel,
                         cudaFuncAttributeMaxDynamicSharedMemorySize, SM_TOT);

    // bucket sort (independent of fused; serial stream)
    zero_kernel<<<1, 1024>>>();
    hist_kernel<<<(N_EDGES + HIST_EPB - 1) / HIST_EPB, 256>>>(arcs);
    scan_kernel<<<1, 1024>>>();
    scatter_kernel<<<(N_EDGES + 255) / 256, 256>>>(arcs);

    fused_kernel<<<GRID, NTHREADS, SM_TOT>>>(z, w1, b1, w2, b2, bw, nw, nb,
                                             h2buf, g1buf, N_NODES);

    edge2_kernel<<<NBUCK, 256>>>(g1buf, h2buf, bb, out);
}

// round 17
// speedup vs baseline: 2.0996x; 2.0996x over previous
#include <cuda_runtime.h>
#include <cuda_fp16.h>
#include <cstdint>

#define N_NODES 50000
#define D 128
#define N_EDGES 500000
#define TILE_M 128
#define NTILES ((N_NODES + TILE_M - 1) / TILE_M)   // 391
#define GRID   148
#define NTHREADS 512

// Scratch (no cudaMalloc). H2/G1 stored fp16 (halves edge-gather traffic).
__device__ __half g_bufH2[N_NODES * D];
__device__ __half g_bufG1[N_NODES * D];

// ---- smem (bytes). fp16 tiles, 136 halves/row ----
#define HS     136
#define SM_ZN  0
#define SM_H1  34816
#define SM_W1  69632
#define SM_W2  104448
#define SM_BW  139264
#define SM_PAR 174080                // 512 floats
#define SM_RED 176128                // 1024 floats (sum1,sq1,sum2,sq2 x256)
#define SM_TOT 180224                // 1 CTA/SM

__device__ __forceinline__ void mma_f16(float& d0, float& d1, float& d2, float& d3,
                                        uint32_t a0, uint32_t a1, uint32_t a2,
                                        uint32_t a3, uint32_t b0, uint32_t b1) {
    asm volatile(
        "mma.sync.aligned.m16n8k16.row.col.f32.f16.f16.f32 "
        "{%0,%1,%2,%3}, {%4,%5,%6,%7}, {%8,%9}, {%0,%1,%2,%3};"
        : "+f"(d0), "+f"(d1), "+f"(d2), "+f"(d3)
        : "r"(a0), "r"(a1), "r"(a2), "r"(a3), "r"(b0), "r"(b1));
}

#define LDMATRIX_X4(r0, r1, r2, r3, addr)                                   \
    asm volatile(                                                           \
        "ldmatrix.sync.aligned.m8n8.x4.shared.b16 {%0,%1,%2,%3}, [%4];"     \
        : "=r"(r0), "=r"(r1), "=r"(r2), "=r"(r3) : "r"(addr))

__device__ __forceinline__ uint32_t smem_u32(const void* p) {
    return (uint32_t)__cvta_generic_to_shared(p);
}

__device__ __forceinline__ float warp_sum(float v) {
#pragma unroll
    for (int o = 16; o > 0; o >>= 1) v += __shfl_xor_sync(0xffffffffu, v, o);
    return v;
}

// Single-B mainloop (pass 3): warp tile 16 rows x 64 cols.
__device__ __forceinline__ void mma_pass(const __half* __restrict__ A,
                                         const __half* __restrict__ B,
                                         float acc[8][4],
                                         int wr, int wc, int lane) {
#pragma unroll
    for (int nt = 0; nt < 8; nt++)
#pragma unroll
        for (int j = 0; j < 4; j++) acc[nt][j] = 0.f;

    const int a_row_off = lane & 15;
    const int a_col     = (lane >> 4) * 8;
    const int b_row_off = (lane & 7) + ((lane >= 16) ? 8 : 0);
    const int b_col     = (lane & 8) ? 8 : 0;

    uint32_t aAddr = smem_u32(&A[(wr * 16 + a_row_off) * HS + a_col]);
    uint32_t bAddr[4];
#pragma unroll
    for (int p = 0; p < 4; p++)
        bAddr[p] = smem_u32(&B[(wc * 64 + p * 16 + b_row_off) * HS + b_col]);

#pragma unroll
    for (int kk = 0; kk < 8; kk++) {
        const uint32_t koff = kk * 32;
        uint32_t a0, a1, a2, a3;
        LDMATRIX_X4(a0, a1, a2, a3, aAddr + koff);
        uint32_t b[4][4];
#pragma unroll
        for (int p = 0; p < 4; p++)
            LDMATRIX_X4(b[p][0], b[p][1], b[p][2], b[p][3], bAddr[p] + koff);
#pragma unroll
        for (int p = 0; p < 4; p++)
#pragma unroll
            for (int sub = 0; sub < 2; sub++) {
                int nt = 2 * p + sub;
                mma_f16(acc[nt][0], acc[nt][1], acc[nt][2], acc[nt][3],
                        a0, a1, a2, a3, b[p][2 * sub], b[p][2 * sub + 1]);
            }
    }
}

// Dual-B mainloop (passes 1+2 fused): A fragments loaded ONCE, two acc sets.
__device__ __forceinline__ void mma_pass_dual(const __half* __restrict__ A,
                                              const __half* __restrict__ B1,
                                              const __half* __restrict__ B2,
                                              float acc1[8][4], float acc2[8][4],
                                              int wr, int wc, int lane) {
#pragma unroll
    for (int nt = 0; nt < 8; nt++)
#pragma unroll
        for (int j = 0; j < 4; j++) { acc1[nt][j] = 0.f; acc2[nt][j] = 0.f; }

    const int a_row_off = lane & 15;
    const int a_col     = (lane >> 4) * 8;
    const int b_row_off = (lane & 7) + ((lane >= 16) ? 8 : 0);
    const int b_col     = (lane & 8) ? 8 : 0;

    uint32_t aAddr = smem_u32(&A[(wr * 16 + a_row_off) * HS + a_col]);
    uint32_t b1Addr[4], b2Addr[4];
#pragma unroll
    for (int p = 0; p < 4; p++) {
        int roff = (wc * 64 + p * 16 + b_row_off) * HS + b_col;
        b1Addr[p] = smem_u32(&B1[roff]);
        b2Addr[p] = smem_u32(&B2[roff]);
    }

#pragma unroll
    for (int kk = 0; kk < 8; kk++) {
        const uint32_t koff = kk * 32;
        uint32_t a0, a1, a2, a3;
        LDMATRIX_X4(a0, a1, a2, a3, aAddr + koff);
#pragma unroll
        for (int p = 0; p < 4; p++) {
            uint32_t b0r, b1r, b2r, b3r;
            LDMATRIX_X4(b0r, b1r, b2r, b3r, b1Addr[p] + koff);
            mma_f16(acc1[2*p][0], acc1[2*p][1], acc1[2*p][2], acc1[2*p][3],
                    a0, a1, a2, a3, b0r, b1r);
            mma_f16(acc1[2*p+1][0], acc1[2*p+1][1], acc1[2*p+1][2], acc1[2*p+1][3],
                    a0, a1, a2, a3, b2r, b3r);
        }
#pragma unroll
        for (int p = 0; p < 4; p++) {
            uint32_t b0r, b1r, b2r, b3r;
            LDMATRIX_X4(b0r, b1r, b2r, b3r, b2Addr[p] + koff);
            mma_f16(acc2[2*p][0], acc2[2*p][1], acc2[2*p][2], acc2[2*p][3],
                    a0, a1, a2, a3, b0r, b1r);
            mma_f16(acc2[2*p+1][0], acc2[2*p+1][1], acc2[2*p+1][2], acc2[2*p+1][3],
                    a0, a1, a2, a3, b2r, b3r);
        }
    }
}

// Dual epilogue: relu+bias+LN for BOTH accumulator sets with ONE sync.
// acc1 -> H1 smem (fp16), acc2 -> gmem H2 (fp16). Per-value arithmetic order
// identical to the split version.
__device__ __forceinline__ void epilogue_dual(
    float acc1[8][4], float acc2[8][4],
    const float* __restrict__ s_b1, const float* __restrict__ s_b2,
    const float* __restrict__ s_nw, const float* __restrict__ s_nb,
    float* __restrict__ red, __half* __restrict__ H1,
    __half* __restrict__ h2_out,
    int row0, int nrows, int wr, int wc, int q, int tig) {
    float* red_sum1 = red;
    float* red_sq1  = red + 256;
    float* red_sum2 = red + 512;
    float* red_sq2  = red + 768;

    float su1[2] = {0.f, 0.f}, sl1[2] = {0.f, 0.f};
    float su2[2] = {0.f, 0.f}, sl2[2] = {0.f, 0.f};
#pragma unroll
    for (int nt = 0; nt < 8; nt++) {
        int c = wc * 64 + nt * 8 + 2 * tig;
        // set 1 (W1 / b1)
        {
            float x0 = fmaxf(acc1[nt][0] + s_b1[c], 0.f);
            float x1 = fmaxf(acc1[nt][1] + s_b1[c + 1], 0.f);
            float y0 = fmaxf(acc1[nt][2] + s_b1[c], 0.f);
            float y1 = fmaxf(acc1[nt][3] + s_b1[c + 1], 0.f);
            acc1[nt][0] = x0; acc1[nt][1] = x1; acc1[nt][2] = y0; acc1[nt][3] = y1;
            su1[0] += x0 + x1; sl1[0] += x0 * x0 + x1 * x1;
            su1[1] += y0 + y1; sl1[1] += y0 * y0 + y1 * y1;
        }
        // set 2 (W2 / b2)
        {
            float x0 = fmaxf(acc2[nt][0] + s_b2[c], 0.f);
            float x1 = fmaxf(acc2[nt][1] + s_b2[c + 1], 0.f);
            float y0 = fmaxf(acc2[nt][2] + s_b2[c], 0.f);
            float y1 = fmaxf(acc2[nt][3] + s_b2[c + 1], 0.f);
            acc2[nt][0] = x0; acc2[nt][1] = x1; acc2[nt][2] = y0; acc2[nt][3] = y1;
            su2[0] += x0 + x1; sl2[0] += x0 * x0 + x1 * x1;
            su2[1] += y0 + y1; sl2[1] += y0 * y0 + y1 * y1;
        }
    }
#pragma unroll
    for (int o = 1; o <= 2; o <<= 1)
#pragma unroll
        for (int h = 0; h < 2; h++) {
            su1[h] += __shfl_xor_sync(0xffffffffu, su1[h], o);
            sl1[h] += __shfl_xor_sync(0xffffffffu, sl1[h], o);
            su2[h] += __shfl_xor_sync(0xffffffffu, su2[h], o);
            sl2[h] += __shfl_xor_sync(0xffffffffu, sl2[h], o);
        }
    if (tig == 0) {
#pragma unroll
        for (int h = 0; h < 2; h++) {
            int r = wr * 16 + q + h * 8;
            red_sum1[wc * 128 + r] = su1[h];
            red_sq1[wc * 128 + r]  = sl1[h];
            red_sum2[wc * 128 + r] = su2[h];
            red_sq2[wc * 128 + r]  = sl2[h];
        }
    }
    __syncthreads();
    float mu1[2], rs1[2], mu2[2], rs2[2];
#pragma unroll
    for (int h = 0; h < 2; h++) {
        int r = wr * 16 + q + h * 8;
        float ts = red_sum1[r] + red_sum1[128 + r];
        float tq = red_sq1[r] + red_sq1[128 + r];
        float m = ts * (1.0f / 128.0f);
        mu1[h] = m;
        rs1[h] = rsqrtf(tq * (1.0f / 128.0f) - m * m + 1e-5f);
        ts = red_sum2[r] + red_sum2[128 + r];
        tq = red_sq2[r] + red_sq2[128 + r];
        m = ts * (1.0f / 128.0f);
        mu2[h] = m;
        rs2[h] = rsqrtf(tq * (1.0f / 128.0f) - m * m + 1e-5f);
    }
#pragma unroll
    for (int nt = 0; nt < 8; nt++) {
        int c = wc * 64 + nt * 8 + 2 * tig;
        float nw0 = s_nw[c], nw1 = s_nw[c + 1];
        float nb0 = s_nb[c], nb1 = s_nb[c + 1];
#pragma unroll
        for (int h = 0; h < 2; h++) {
            int r = wr * 16 + q + h * 8;
            // H1 -> smem
            float v0 = (acc1[nt][2 * h]     - mu1[h]) * rs1[h] * nw0 + nb0;
            float v1 = (acc1[nt][2 * h + 1] - mu1[h]) * rs1[h] * nw1 + nb1;
            *reinterpret_cast<__half2*>(&H1[r * HS + c]) = __floats2half2_rn(v0, v1);
            // H2 -> gmem
            int gr = row0 + r;
            if (gr < nrows) {
                float u0 = (acc2[nt][2 * h]     - mu2[h]) * rs2[h] * nw0 + nb0;
                float u1 = (acc2[nt][2 * h + 1] - mu2[h]) * rs2[h] * nw1 + nb1;
                *reinterpret_cast<__half2*>(h2_out + (size_t)gr * D + c) =
                    __floats2half2_rn(u0, u1);
            }
        }
    }
}

// Persistent fused kernel: 148 CTAs x 512 threads, all weights resident.
__global__ void __launch_bounds__(NTHREADS, 1) fused_kernel(
    const float* __restrict__ z,
    const float* __restrict__ w1, const float* __restrict__ b1,
    const float* __restrict__ w2, const float* __restrict__ b2,
    const float* __restrict__ bw,
    const float* __restrict__ nw, const float* __restrict__ nb,
    __half* __restrict__ h2_out, __half* __restrict__ g1_out, int nrows) {
    extern __shared__ char smem[];
    __half* ZNh = reinterpret_cast<__half*>(smem + SM_ZN);
    __half* H1h = reinterpret_cast<__half*>(smem + SM_H1);
    __half* W1h = reinterpret_cast<__half*>(smem + SM_W1);
    __half* W2h = reinterpret_cast<__half*>(smem + SM_W2);
    __half* BWh = reinterpret_cast<__half*>(smem + SM_BW);
    float*  par = reinterpret_cast<float*>(smem + SM_PAR);
    float*  red = reinterpret_cast<float*>(smem + SM_RED);

    const int tid  = threadIdx.x;
    const int lane = tid & 31;
    const int w    = tid >> 5;
    const int q    = lane >> 2;
    const int tig  = lane & 3;
    const int wr   = w & 7;
    const int wc   = w >> 3;

    // ---- stage ALL weights + params ONCE ----
    if (tid < 512)
        par[tid] = (tid < 128)   ? b1[tid]
                 : (tid < 256)   ? b2[tid - 128]
                 : (tid < 384)   ? nw[tid - 256]
                                 : nb[tid - 384];
#pragma unroll
    for (int i = 0; i < 8; i++) {
        int idx = tid + i * NTHREADS;
        int r = idx >> 5, c4 = idx & 31;
        float4 v1 = reinterpret_cast<const float4*>(w1)[idx];
        float4 v2 = reinterpret_cast<const float4*>(w2)[idx];
        int off = r * HS + c4 * 4;
        *reinterpret_cast<__half2*>(&W1h[off])     = __floats2half2_rn(v1.x, v1.y);
        *reinterpret_cast<__half2*>(&W1h[off + 2]) = __floats2half2_rn(v1.z, v1.w);
        *reinterpret_cast<__half2*>(&W2h[off])     = __floats2half2_rn(v2.x, v2.y);
        *reinterpret_cast<__half2*>(&W2h[off + 2]) = __floats2half2_rn(v2.z, v2.w);
    }
    // BW^T: BWh[f][d] = bw[d][f]
#pragma unroll
    for (int i = 0; i < 32; i++) {
        int idx = tid + i * NTHREADS;
        int d = idx >> 7, f = idx & 127;
        BWh[f * HS + d] = __float2half_rn(bw[idx]);
    }
    __syncthreads();

    const float* s_b1 = par;
    const float* s_b2 = par + 128;
    const float* s_nw = par + 256;
    const float* s_nb = par + 384;

    float4 lnw4 = reinterpret_cast<const float4*>(s_nw)[lane];
    float4 lnb4 = reinterpret_cast<const float4*>(s_nb)[lane];

    // ---- persistent tile loop ----
    for (int t = blockIdx.x; t < NTILES; t += GRID) {
        const int row0 = t * TILE_M;

        // LN(z) staged to fp16 ZN (warp w: rows w*8 .. w*8+7; 2 MLP-4 batches)
#pragma unroll
        for (int bb2 = 0; bb2 < 2; bb2++) {
            float4 v[4];
#pragma unroll
            for (int i = 0; i < 4; i++) {
                int gr = row0 + w * 8 + bb2 * 4 + i;
                v[i] = (gr < nrows)
                         ? reinterpret_cast<const float4*>(z)[(size_t)gr * 32 + lane]
                         : make_float4(0.f, 0.f, 0.f, 0.f);
            }
#pragma unroll
            for (int i = 0; i < 4; i++) {
                int r = w * 8 + bb2 * 4 + i;
                float s  = warp_sum(v[i].x + v[i].y + v[i].z + v[i].w);
                float sq = warp_sum(v[i].x * v[i].x + v[i].y * v[i].y +
                                    v[i].z * v[i].z + v[i].w * v[i].w);
                float mu = s * (1.0f / 128.0f);
                float rs = rsqrtf(sq * (1.0f / 128.0f) - mu * mu + 1e-5f);
                float o0 = (v[i].x - mu) * rs * lnw4.x + lnb4.x;
                float o1 = (v[i].y - mu) * rs * lnw4.y + lnb4.y;
                float o2 = (v[i].z - mu) * rs * lnw4.z + lnb4.z;
                float o3 = (v[i].w - mu) * rs * lnw4.w + lnb4.w;
                int off = r * HS + lane * 4;
                *reinterpret_cast<__half2*>(&ZNh[off])     = __floats2half2_rn(o0, o1);
                *reinterpret_cast<__half2*>(&ZNh[off + 2]) = __floats2half2_rn(o2, o3);
            }
        }
        __syncthreads();   // ZN ready (also fences prior pass3 H1 reads)

        float acc1[8][4], acc2[8][4];

        // PASSES 1+2 fused off one A-fragment load
        mma_pass_dual(ZNh, W1h, W2h, acc1, acc2, wr, wc, lane);

        // dual epilogue: acc1 -> H1 smem, acc2 -> gmem H2 (one internal sync)
        epilogue_dual(acc1, acc2, s_b1, s_b2, s_nw, s_nb, red, H1h, h2_out,
                      row0, nrows, wr, wc, q, tig);
        __syncthreads();   // H1 writes visible for pass 3

        // PASS 3: G1 = H1 @ bil_w -> gmem (fp16)
        mma_pass(H1h, BWh, acc1, wr, wc, lane);
#pragma unroll
        for (int nt = 0; nt < 8; nt++) {
            int c = wc * 64 + nt * 8 + 2 * tig;
#pragma unroll
            for (int h = 0; h < 2; h++) {
                int gr = row0 + wr * 16 + q + h * 8;
                if (gr < nrows)
                    *reinterpret_cast<__half2*>(g1_out + (size_t)gr * D + c) =
                        __floats2half2_rn(acc1[nt][2 * h], acc1[nt][2 * h + 1]);
            }
        }
    }
}

// ---------------------------------------------------------------------------
// Edge kernel (R15/R12 version — at L2 roofline): 16 edges/warp, 8 lanes/edge,
// full 128B wavefronts, 16 independent L2-only loads per lane.
// ---------------------------------------------------------------------------
__global__ void __launch_bounds__(256) edge_kernel(
    const int* __restrict__ arcs,
    const __half* __restrict__ G1,
    const __half* __restrict__ H2,
    const float* __restrict__ bilb,
    float* __restrict__ out) {
    const int warp = (blockIdx.x * blockDim.x + threadIdx.x) >> 5;
    const int lane = threadIdx.x & 31;
    const int j    = lane >> 3;
    const int s    = lane & 7;
    const int e0   = warp * 16 + j;
    if (e0 >= N_EDGES) return;

    int2 a[4];
#pragma unroll
    for (int b = 0; b < 4; b++)
        a[b] = __ldg(reinterpret_cast<const int2*>(arcs) + e0 + 4 * b);

    float4 g[4][2], h[4][2];
#pragma unroll
    for (int b = 0; b < 4; b++) {
        const float4* g4 = reinterpret_cast<const float4*>(G1 + (size_t)a[b].x * D);
        const float4* h4 = reinterpret_cast<const float4*>(H2 + (size_t)a[b].y * D);
        g[b][0] = __ldcg(g4 + s);
        g[b][1] = __ldcg(g4 + s + 8);
        h[b][0] = __ldcg(h4 + s);
        h[b][1] = __ldcg(h4 + s + 8);
    }
#pragma unroll
    for (int b = 0; b < 4; b++) {
        float v = 0.f;
#pragma unroll
        for (int p = 0; p < 2; p++) {
            const __half2* gh = reinterpret_cast<const __half2*>(&g[b][p]);
            const __half2* hh = reinterpret_cast<const __half2*>(&h[b][p]);
#pragma unroll
            for (int k = 0; k < 4; k++) {
                float2 gf = __half22float2(gh[k]);
                float2 hf = __half22float2(hh[k]);
                v += gf.x * hf.x + gf.y * hf.y;
            }
        }
        v += __shfl_xor_sync(0xffffffffu, v, 1);
        v += __shfl_xor_sync(0xffffffffu, v, 2);
        v += __shfl_xor_sync(0xffffffffu, v, 4);
        if (s == 0) out[e0 + 4 * b] = v + bilb[0];
    }
}

// ---------------------------------------------------------------------------
extern "C" void kernel_launch(void* const* d_in, const int* in_sizes, int n_in,
                              void* d_out, int out_size) {
    const float* z    = (const float*)d_in[0];
    const int*   arcs = (const int*)d_in[1];
    const float* w1   = (const float*)d_in[2];
    const float* b1   = (const float*)d_in[3];
    const float* w2   = (const float*)d_in[4];
    const float* b2   = (const float*)d_in[5];
    const float* bw   = (const float*)d_in[6];
    const float* bb   = (const float*)d_in[7];
    const float* nw   = (const float*)d_in[8];
    const float* nb   = (const float*)d_in[9];
    float*       out  = (float*)d_out;

    __half *h2buf, *g1buf;
    cudaGetSymbolAddress((void**)&h2buf, g_bufH2);
    cudaGetSymbolAddress((void**)&g1buf, g_bufG1);

    cudaFuncSetAttribute(fused_kernel,
                         cudaFuncAttributeMaxDynamicSharedMemorySize, SM_TOT);

    fused_kernel<<<GRID, NTHREADS, SM_TOT>>>(z, w1, b1, w2, b2, bw, nw, nb,
                                             h2buf, g1buf, N_NODES);
    edge_kernel<<<(N_EDGES + 127) / 128, 256>>>(arcs, g1buf, h2buf, bb, out);
}